// round 1
// baseline (speedup 1.0000x reference)
#include <cuda_runtime.h>
#include <math.h>

typedef unsigned long long ull;

// ---------- f32x2 packed-fp32 helpers (sm_100+) ----------
__device__ __forceinline__ ull pk2(float lo, float hi) {
    ull r; asm("mov.b64 %0,{%1,%2};" : "=l"(r) : "f"(lo), "f"(hi)); return r;
}
__device__ __forceinline__ void upk2(ull v, float& lo, float& hi) {
    asm("mov.b64 {%0,%1},%2;" : "=f"(lo), "=f"(hi) : "l"(v));
}
__device__ __forceinline__ ull ffma2(ull a, ull b, ull c) {
    ull d; asm("fma.rn.f32x2 %0,%1,%2,%3;" : "=l"(d) : "l"(a), "l"(b), "l"(c)); return d;
}

// ---------- problem constants ----------
#define BATCH   64
#define SEQ     2048
#define FEAT    256
#define HID     256
#define G4      1024           // 4*HID
#define NGROUP  16             // batch groups (4 batches each)
#define NCTA_PG 8              // CTAs per group (each owns 128 gate cols)
#define BG      4              // batches per group

// ---------- scratch (no cudaMalloc allowed) ----------
__device__ float    xp_buf[(size_t)BATCH * SEQ * G4];      // 512 MB: x @ Wx + bx + bh
__device__ float    h_buf[NGROUP * 2 * HID * BG];          // double-buffered h, layout [grp][p][k][b]
__device__ unsigned bar_arr[NGROUP];

// ============================================================
// init: zero h buffers + barrier counters (graph replays rerun this)
// ============================================================
__global__ void init_kernel() {
    int t = blockIdx.x * blockDim.x + threadIdx.x;
    if (t < NGROUP * 2 * HID * BG) h_buf[t] = 0.0f;
    if (t < NGROUP) bar_arr[t] = 0u;
}

// ============================================================
// x_proj GEMM: xp[bt, g] = sum_f x[bt,f]*Wx[f,g] + Bx[g] + Bh[g]
// 64x64 block tile, 4x4 thread tile, f32x2 FMA
// ============================================================
__global__ __launch_bounds__(256) void xproj_kernel(
    const float* __restrict__ x, const float* __restrict__ WX,
    const float* __restrict__ BX, const float* __restrict__ BH)
{
    __shared__ float xs[64][68];   // [k][row], padded
    __shared__ float ws[64][64];   // [k][col]

    const int tid = threadIdx.x;
    const int ty = tid >> 4, tx = tid & 15;
    const size_t row0 = (size_t)blockIdx.x * 64;
    const int col0 = blockIdx.y * 64;

    ull acc[4][2];
#pragma unroll
    for (int i = 0; i < 4; i++) { acc[i][0] = pk2(0.f, 0.f); acc[i][1] = pk2(0.f, 0.f); }

    for (int kc = 0; kc < FEAT; kc += 64) {
#pragma unroll
        for (int i = 0; i < 4; i++) {
            int r = (tid >> 4) + 16 * i;
            float4 v = *(const float4*)&x[(row0 + r) * FEAT + kc + (tid & 15) * 4];
            int kb = (tid & 15) * 4;
            xs[kb + 0][r] = v.x; xs[kb + 1][r] = v.y;
            xs[kb + 2][r] = v.z; xs[kb + 3][r] = v.w;
        }
#pragma unroll
        for (int i = 0; i < 4; i++) {
            int kk = (tid >> 4) + 16 * i;
            float4 v = *(const float4*)&WX[(size_t)(kc + kk) * G4 + col0 + (tid & 15) * 4];
            *(float4*)&ws[kk][(tid & 15) * 4] = v;
        }
        __syncthreads();
#pragma unroll 16
        for (int kk = 0; kk < 64; kk++) {
            float4 a4 = *(const float4*)&xs[kk][4 * ty];
            float4 b4 = *(const float4*)&ws[kk][4 * tx];
            ull b01 = pk2(b4.x, b4.y), b23 = pk2(b4.z, b4.w);
            ull am;
            am = pk2(a4.x, a4.x); acc[0][0] = ffma2(am, b01, acc[0][0]); acc[0][1] = ffma2(am, b23, acc[0][1]);
            am = pk2(a4.y, a4.y); acc[1][0] = ffma2(am, b01, acc[1][0]); acc[1][1] = ffma2(am, b23, acc[1][1]);
            am = pk2(a4.z, a4.z); acc[2][0] = ffma2(am, b01, acc[2][0]); acc[2][1] = ffma2(am, b23, acc[2][1]);
            am = pk2(a4.w, a4.w); acc[3][0] = ffma2(am, b01, acc[3][0]); acc[3][1] = ffma2(am, b23, acc[3][1]);
        }
        __syncthreads();
    }

    const int gc = col0 + 4 * tx;
    float4 bx4 = *(const float4*)&BX[gc];
    float4 bh4 = *(const float4*)&BH[gc];
    float4 bias = make_float4(bx4.x + bh4.x, bx4.y + bh4.y, bx4.z + bh4.z, bx4.w + bh4.w);
#pragma unroll
    for (int i = 0; i < 4; i++) {
        float4 o;
        upk2(acc[i][0], o.x, o.y);
        upk2(acc[i][1], o.z, o.w);
        o.x += bias.x; o.y += bias.y; o.z += bias.z; o.w += bias.w;
        *(float4*)&xp_buf[(row0 + 4 * ty + i) * G4 + gc] = o;
    }
}

// ============================================================
// LSTM recurrence: 128 persistent CTAs = 16 groups x 8 CTAs.
// Group g handles batches [4g, 4g+4). CTA r in group holds
// WeightH cols {gate*256 + 32r + jj : gate<4, jj<32} in SMEM (128KB).
// Per step: 4x128x256 sub-GEMM (f32x2, 8-way K-split) -> smem
// reduction -> gates -> c/h update -> h broadcast via L2 + group
// spin barrier (monotonic counter, double-buffered h).
// ============================================================
__device__ __forceinline__ float fsig(float x) { return 1.0f / (1.0f + __expf(-x)); }
__device__ __forceinline__ float ftanh(float x) { return 2.0f * fsig(2.0f * x) - 1.0f; }

__global__ __launch_bounds__(256, 1) void lstm_kernel(
    float* __restrict__ out, const float* __restrict__ WH, long long out_size)
{
    extern __shared__ float sm[];
    float*  WH_s    = sm;                                   // 32768 floats (128 KB)
    float4* h_s     = (float4*)(sm + 32768);                // 256 float4  (4 KB)
    ull*    red     = (ull*)(sm + 32768 + 1024);            // 256*10 ull  (20 KB, stride-padded)
    float*  gates_s = sm + 32768 + 1024 + 5120;             // 512 floats  (2 KB)

    const int tid = threadIdx.x;
    const int grp = blockIdx.x >> 3;
    const int r   = blockIdx.x & 7;
    const int batch0 = grp * BG;

    // ---- load WeightH slice into SMEM ----
    for (int idx = tid; idx < HID * 128; idx += 256) {
        int k = idx >> 7, c = idx & 127;
        int gc = (c >> 5) * HID + 32 * r + (c & 31);
        WH_s[idx] = WH[(size_t)k * G4 + gc];
    }

    const int ks = tid >> 5;      // K-split id 0..7 (k in [32ks, 32ks+32))
    const int cq = tid & 31;      // col-quad 0..31 (local cols 4cq..4cq+3)
    // phase A (tid<128): pacq = tid>>2 colquad, pab = tid&3 batch
    // phase B (tid<128): pbb = tid>>5 batch,    jj = tid&31 hidden unit
    const int pacq = tid >> 2, pab = tid & 3;
    const int pbb  = tid >> 5, jj  = tid & 31;

    float cstate = 0.0f;
    float hlast  = 0.0f;
    const float4* hb4 = (const float4*)h_buf;
    volatile unsigned* vb = bar_arr;

    __syncthreads();

    int p = 0;
    for (int t = 0; t < SEQ; t++) {
        // ---- gather h (written by all 8 group CTAs) : must bypass L1 ----
        float4 hv = __ldcg(&hb4[(grp * 2 + p) * HID + tid]);
        h_s[tid] = hv;

        // ---- prefetch this step's x_proj slice (consumed ~1.5k cyc later) ----
        float4 xp4 = make_float4(0.f, 0.f, 0.f, 0.f);
        if (tid < 128) {
            int gate = pacq >> 3;
            int cb   = (4 * pacq) & 31;
            size_t xoff = ((size_t)(batch0 + pab) * SEQ + t) * G4 + gate * HID + 32 * r + cb;
            xp4 = *(const float4*)&xp_buf[xoff];
        }
        __syncthreads();

        // ---- sub-GEMM: gates_part[b][4cq..4cq+3] over k in [32ks,32ks+32) ----
        ull a00 = pk2(0.f,0.f), a01 = a00, a10 = a00, a11 = a00;
        ull a20 = a00, a21 = a00, a30 = a00, a31 = a00;
        {
            const float4* wp = (const float4*)&WH_s[(size_t)ks * 32 * 128];
            const float4* hp = h_s + ks * 32;
#pragma unroll 8
            for (int kk = 0; kk < 32; kk++) {
                float4 h4 = hp[kk];
                float4 w4 = wp[kk * 32 + cq];
                ull w01 = pk2(w4.x, w4.y), w23 = pk2(w4.z, w4.w);
                ull hm;
                hm = pk2(h4.x, h4.x); a00 = ffma2(hm, w01, a00); a01 = ffma2(hm, w23, a01);
                hm = pk2(h4.y, h4.y); a10 = ffma2(hm, w01, a10); a11 = ffma2(hm, w23, a11);
                hm = pk2(h4.z, h4.z); a20 = ffma2(hm, w01, a20); a21 = ffma2(hm, w23, a21);
                hm = pk2(h4.w, h4.w); a30 = ffma2(hm, w01, a30); a31 = ffma2(hm, w23, a31);
            }
        }
        {   // stage partials: per-thread stride 10 ull (80B) to dodge worst bank pattern
            ull* rp = red + (size_t)tid * 10;
            ((ulonglong2*)rp)[0] = make_ulonglong2(a00, a01);
            ((ulonglong2*)rp)[1] = make_ulonglong2(a10, a11);
            ((ulonglong2*)rp)[2] = make_ulonglong2(a20, a21);
            ((ulonglong2*)rp)[3] = make_ulonglong2(a30, a31);
        }
        __syncthreads();

        // ---- phase A: reduce 8 K-splits, add x_proj, stage gates ----
        if (tid < 128) {
            float4 s = xp4;
#pragma unroll
            for (int j = 0; j < 8; j++) {
                float4 v = *(const float4*)&red[(size_t)(j * 32 + pacq) * 10 + pab * 2];
                s.x += v.x; s.y += v.y; s.z += v.z; s.w += v.w;
            }
            *(float4*)&gates_s[pab * 128 + 4 * pacq] = s;
        }
        __syncthreads();

        // ---- phase B: activations + state update + writes ----
        if (tid < 128) {
            float gi = gates_s[pbb * 128 +       jj];
            float gf = gates_s[pbb * 128 +  32 + jj];
            float gg = gates_s[pbb * 128 +  64 + jj];
            float go = gates_s[pbb * 128 +  96 + jj];
            float i_ = fsig(gi), f_ = fsig(gf), g_ = ftanh(gg), o_ = fsig(go);
            cstate = f_ * cstate + i_ * g_;
            float h_ = o_ * ftanh(cstate);
            hlast = h_;
            int kidx = 32 * r + jj;
            h_buf[(((grp * 2 + (p ^ 1)) * HID) + kidx) * BG + pbb] = h_;
            out[((size_t)(batch0 + pbb) * SEQ + t) * HID + kidx] = h_;
            __threadfence();   // release h writes to L2 before group arrive
        }
        __syncthreads();

        // ---- group barrier: monotonic counter, thread0 spins ----
        if (tid == 0) {
            atomicAdd(&bar_arr[grp], 1u);
            unsigned target = (unsigned)(NCTA_PG) * (unsigned)(t + 1);
            while (vb[grp] < target) { }
            __threadfence();   // acquire
        }
        __syncthreads();
        p ^= 1;
    }

    // ---- h_n (second output), if the harness buffer includes it ----
    if (tid < 128 && out_size >= (long long)BATCH * SEQ * HID + BATCH * HID) {
        out[(size_t)BATCH * SEQ * HID + (size_t)(batch0 + pbb) * HID + 32 * r + jj] = hlast;
    }
}

// ============================================================
extern "C" void kernel_launch(void* const* d_in, const int* in_sizes, int n_in,
                              void* d_out, int out_size)
{
    const float* x  = (const float*)d_in[0];
    const float* WX = (const float*)d_in[1];
    const float* WH = (const float*)d_in[2];
    const float* BX = (const float*)d_in[3];
    const float* BH = (const float*)d_in[4];
    float* out = (float*)d_out;

    const size_t lstm_smem = (32768 + 1024 + 5120 + 512) * sizeof(float); // 157,696 B
    cudaFuncSetAttribute(lstm_kernel, cudaFuncAttributeMaxDynamicSharedMemorySize, (int)lstm_smem);

    init_kernel<<<128, 256>>>();

    dim3 gx((BATCH * SEQ) / 64, G4 / 64);
    xproj_kernel<<<gx, 256>>>(x, WX, BX, BH);

    lstm_kernel<<<NGROUP * NCTA_PG, 256, lstm_smem>>>(out, WH, (long long)out_size);
}